// round 1
// baseline (speedup 1.0000x reference)
#include <cuda_runtime.h>

#define N_NODES 16384
#define N_EDGES 262144
#define D_CH    256
#define BN_EPS  1e-5f

// ---------------- scratch (device globals; no runtime allocation) ----------
__device__ float g_emb[N_NODES * D_CH];
__device__ float g_xn [N_NODES * D_CH];
__device__ float g_r  [N_NODES * D_CH];
__device__ float g_q  [N_NODES * D_CH];
__device__ float g_h  [N_NODES * D_CH];

__device__ float g_sum[D_CH];
__device__ float g_sq [D_CH];
__device__ float g_scale[D_CH];
__device__ float g_shift[D_CH];

__device__ int g_deg[N_NODES];
__device__ int g_off[N_NODES + 1];
__device__ int g_cur[N_NODES];
__device__ int g_csr[N_EDGES];

// ---------------- CSR construction ----------------------------------------
__global__ void zero_deg_k() {
    int i = blockIdx.x * 256 + threadIdx.x;
    if (i < N_NODES) g_deg[i] = 0;
}

__global__ void hist_k(const int* __restrict__ ei) {
    int e = blockIdx.x * 256 + threadIdx.x;
    if (e < N_EDGES) atomicAdd(&g_deg[ei[N_EDGES + e]], 1);
}

// exclusive scan of 16384 ints, single block of 1024 threads, 16 elems each
__global__ void scan_k() {
    __shared__ int s[1024];
    int t = threadIdx.x;
    int base = t * 16;
    int local[16];
    int sum = 0;
#pragma unroll
    for (int i = 0; i < 16; i++) { local[i] = g_deg[base + i]; sum += local[i]; }
    s[t] = sum;
    __syncthreads();
    // inclusive Hillis-Steele over 1024 partials
    for (int d = 1; d < 1024; d <<= 1) {
        int v = 0;
        if (t >= d) v = s[t - d];
        __syncthreads();
        if (t >= d) s[t] += v;
        __syncthreads();
    }
    int prefix = (t == 0) ? 0 : s[t - 1];
    int run = prefix;
#pragma unroll
    for (int i = 0; i < 16; i++) { g_off[base + i] = run; run += local[i]; }
    if (t == 1023) g_off[N_NODES] = run;
}

__global__ void copy_cur_k() {
    int i = blockIdx.x * 256 + threadIdx.x;
    if (i < N_NODES) g_cur[i] = g_off[i];
}

__global__ void scatter_k(const int* __restrict__ ei) {
    int e = blockIdx.x * 256 + threadIdx.x;
    if (e < N_EDGES) {
        int d = ei[N_EDGES + e];
        int p = atomicAdd(&g_cur[d], 1);
        g_csr[p] = ei[e];
    }
}

// ---------------- SpMM: emb[i] = sum_{j in nbr(i)} ew[j] + eb --------------
// 4 nodes per 256-thread block, 64 threads (float4 lanes) per node.
__global__ void spmm_k(const float* __restrict__ ew,
                       const float* __restrict__ eb,
                       float* __restrict__ emb) {
    int node = blockIdx.x * 4 + (threadIdx.x >> 6);
    int c = threadIdx.x & 63;
    const float4* ew4 = (const float4*)ew;
    float4 acc = ((const float4*)eb)[c];
    int s = g_off[node];
    int e = g_off[node + 1];
    for (int k = s; k < e; k++) {
        int j = g_csr[k];
        float4 v = ew4[j * 64 + c];
        acc.x += v.x; acc.y += v.y; acc.z += v.z; acc.w += v.w;
    }
    ((float4*)emb)[node * 64 + c] = acc;
}

// ---------------- fused GEMMs ----------------------------------------------
// MODE 0: out = A@B1 + bias1                                  (plain, store)
// MODE 1: out = relu(A@B1 + A2@B2 + bias1 + bias2 + A + A2)   (K=512 dual pass)
// MODE 2: out = relu(A@B1 + bias1), accumulate column sum/sumsq into g_sum/g_sq
// MODE 3: out = (A*g_scale[k]+g_shift[k])@B1 + bias1          (BN folded into A)
//
// 128x128 tile, BK=16, 256 threads, 8x8 per thread.
template <int MODE>
__global__ void __launch_bounds__(256, 2)
gemm_k(const float* __restrict__ A, const float* __restrict__ A2,
       const float* __restrict__ B1, const float* __restrict__ B2,
       const float* __restrict__ bias1, const float* __restrict__ bias2,
       float* __restrict__ outp, int ldout) {
    __shared__ float As[16][128];
    __shared__ float Bs[16][128];

    const int bm = blockIdx.y * 128;
    const int bn = blockIdx.x * 128;
    const int tid = threadIdx.x;
    const int tx = tid & 15;   // column group
    const int ty = tid >> 4;   // row group

    float acc[8][8];
#pragma unroll
    for (int i = 0; i < 8; i++)
#pragma unroll
        for (int j = 0; j < 8; j++) acc[i][j] = 0.f;

    const int ar = tid >> 2;         // 0..63
    const int ac = (tid & 3) * 4;    // 0,4,8,12
    const int br = tid >> 5;         // 0..7
    const int bc = (tid & 31) * 4;   // 0..124

    const int npass = (MODE == 1) ? 2 : 1;
    for (int pass = 0; pass < npass; pass++) {
        const float* Ap = pass ? A2 : A;
        const float* Bp = pass ? B2 : B1;
        for (int kt = 0; kt < 256; kt += 16) {
#pragma unroll
            for (int l = 0; l < 2; l++) {
                float4 v = *(const float4*)(Ap + (bm + ar + l * 64) * 256 + kt + ac);
                if (MODE == 3) {
                    v.x = v.x * g_scale[kt + ac + 0] + g_shift[kt + ac + 0];
                    v.y = v.y * g_scale[kt + ac + 1] + g_shift[kt + ac + 1];
                    v.z = v.z * g_scale[kt + ac + 2] + g_shift[kt + ac + 2];
                    v.w = v.w * g_scale[kt + ac + 3] + g_shift[kt + ac + 3];
                }
                As[ac + 0][ar + l * 64] = v.x;
                As[ac + 1][ar + l * 64] = v.y;
                As[ac + 2][ar + l * 64] = v.z;
                As[ac + 3][ar + l * 64] = v.w;
            }
#pragma unroll
            for (int l = 0; l < 2; l++) {
                *(float4*)&Bs[br + l * 8][bc] =
                    *(const float4*)(Bp + (kt + br + l * 8) * 256 + bn + bc);
            }
            __syncthreads();
#pragma unroll
            for (int k = 0; k < 16; k++) {
                float af[8], bf[8];
                *(float4*)(af)     = *(const float4*)&As[k][ty * 8];
                *(float4*)(af + 4) = *(const float4*)&As[k][ty * 8 + 4];
                *(float4*)(bf)     = *(const float4*)&Bs[k][tx * 8];
                *(float4*)(bf + 4) = *(const float4*)&Bs[k][tx * 8 + 4];
#pragma unroll
                for (int i = 0; i < 8; i++)
#pragma unroll
                    for (int j = 0; j < 8; j++)
                        acc[i][j] = fmaf(af[i], bf[j], acc[i][j]);
            }
            __syncthreads();
        }
    }

    // epilogue
    float csum[8], csq[8];
#pragma unroll
    for (int j = 0; j < 8; j++) { csum[j] = 0.f; csq[j] = 0.f; }

#pragma unroll
    for (int i = 0; i < 8; i++) {
        int row = bm + ty * 8 + i;
        float o[8];
#pragma unroll
        for (int j = 0; j < 8; j++) {
            int col = bn + tx * 8 + j;
            float c = acc[i][j] + bias1[col];
            if (MODE == 1) {
                c += bias2[col];
                c += A [row * 256 + col];   // + emb
                c += A2[row * 256 + col];   // + xn
                c = fmaxf(c, 0.f);
            }
            if (MODE == 2) {
                c = fmaxf(c, 0.f);
                csum[j] += c;
                csq[j] += c * c;
            }
            o[j] = c;
        }
        *(float4*)(outp + row * ldout + bn + tx * 8)     = *(float4*)(o);
        *(float4*)(outp + row * ldout + bn + tx * 8 + 4) = *(float4*)(o + 4);
    }

    if (MODE == 2) {
        __syncthreads();
#pragma unroll
        for (int j = 0; j < 8; j++) {
            As[ty][tx * 8 + j] = csum[j];
            Bs[ty][tx * 8 + j] = csq[j];
        }
        __syncthreads();
        if (tid < 128) {
            float s = 0.f, q = 0.f;
#pragma unroll
            for (int t = 0; t < 16; t++) { s += As[t][tid]; q += Bs[t][tid]; }
            atomicAdd(&g_sum[bn + tid], s);
            atomicAdd(&g_sq [bn + tid], q);
        }
    }
}

// ---------------- BN helpers -----------------------------------------------
__global__ void zero_stats_k() {
    int c = threadIdx.x;
    g_sum[c] = 0.f;
    g_sq[c] = 0.f;
}

__global__ void bn_prep_k(const float* __restrict__ gamma,
                          const float* __restrict__ beta) {
    int c = threadIdx.x;
    const float inv_n = 1.f / (float)N_NODES;
    float mu = g_sum[c] * inv_n;
    float var = g_sq[c] * inv_n - mu * mu;
    float rs = rsqrtf(var + BN_EPS);
    g_scale[c] = rs * gamma[c];
    g_shift[c] = beta[c] - mu * rs * gamma[c];
}

// ---------------- concat copy: out[:, 256:512] = x --------------------------
__global__ void copyx_k(const float* __restrict__ x, float* __restrict__ out) {
    int idx = blockIdx.x * 256 + threadIdx.x;  // N*64 float4 lanes
    int m = idx >> 6;
    int c = idx & 63;
    ((float4*)out)[m * 128 + 64 + c] = ((const float4*)x)[m * 64 + c];
}

// ---------------- host orchestration ----------------------------------------
static void run_layer(const float* xin, const float* const* P,
                      float* emb, float* xn, float* r, float* q,
                      float* hout, int ldout) {
    // P: 0 ew, 1 eb, 2 nw, 3 nb, 4 c1w, 5 c1b, 6 c2w, 7 c2b,
    //    8 f1w, 9 f1b, 10 bng, 11 bnb, 12 f2w, 13 f2b
    dim3 grid(2, 128);

    spmm_k<<<N_NODES / 4, 256>>>(P[0], P[1], emb);
    gemm_k<0><<<grid, 256>>>(xin, nullptr, P[2], nullptr, P[3], nullptr, xn, 256);
    gemm_k<1><<<grid, 256>>>(emb, xn, P[4], P[6], P[5], P[7], r, 256);
    zero_stats_k<<<1, 256>>>();
    gemm_k<2><<<grid, 256>>>(r, nullptr, P[8], nullptr, P[9], nullptr, q, 256);
    bn_prep_k<<<1, 256>>>(P[10], P[11]);
    gemm_k<3><<<grid, 256>>>(q, nullptr, P[12], nullptr, P[13], nullptr, hout, ldout);
}

extern "C" void kernel_launch(void* const* d_in, const int* in_sizes, int n_in,
                              void* d_out, int out_size) {
    (void)in_sizes; (void)n_in; (void)out_size;

    const float* x  = (const float*)d_in[0];
    const int*   ei = (const int*)d_in[2];

    const float* P1[14];
    const float* P2[14];
    for (int i = 0; i < 14; i++) {
        P1[i] = (const float*)d_in[4 + i];
        P2[i] = (const float*)d_in[18 + i];
    }

    float *emb, *xn, *r, *q, *h;
    cudaGetSymbolAddress((void**)&emb, g_emb);
    cudaGetSymbolAddress((void**)&xn,  g_xn);
    cudaGetSymbolAddress((void**)&r,   g_r);
    cudaGetSymbolAddress((void**)&q,   g_q);
    cudaGetSymbolAddress((void**)&h,   g_h);

    float* out = (float*)d_out;

    // CSR once (same graph for both layers)
    zero_deg_k<<<N_NODES / 256, 256>>>();
    hist_k<<<N_EDGES / 256, 256>>>(ei);
    scan_k<<<1, 1024>>>();
    copy_cur_k<<<N_NODES / 256, 256>>>();
    scatter_k<<<N_EDGES / 256, 256>>>(ei);

    // layer 1 -> g_h
    run_layer(x, P1, emb, xn, r, q, h, 256);
    // layer 2 -> d_out[:, 0:256] (ld = 512)
    run_layer(h, P2, emb, xn, r, q, out, 512);
    // d_out[:, 256:512] = x
    copyx_k<<<N_NODES * 64 / 256, 256>>>(x, out);
}

// round 2
// speedup vs baseline: 1.0594x; 1.0594x over previous
#include <cuda_runtime.h>

#define N_NODES 16384
#define N_EDGES 262144
#define D_CH    256
#define BN_EPS  1e-5f

// ---------------- scratch (device globals; no runtime allocation) ----------
__device__ float g_emb[N_NODES * D_CH];
__device__ float g_r  [N_NODES * D_CH];
__device__ float g_q  [N_NODES * D_CH];
__device__ float g_h  [N_NODES * D_CH];

__device__ float g_w1p [D_CH * D_CH];   // I + c1w
__device__ float g_c2wp[D_CH * D_CH];   // I + c2w
__device__ float g_wx  [D_CH * D_CH];   // nw @ (I + c2w)
__device__ float g_biasr[D_CH];         // nb@(I+c2w) + c1b + c2b
__device__ float g_zero[D_CH];          // stays 0 (device globals zero-init)

__device__ float g_sum[D_CH];
__device__ float g_sq [D_CH];
__device__ float g_scale[D_CH];
__device__ float g_shift[D_CH];

__device__ int g_deg[N_NODES];
__device__ int g_off[N_NODES + 1];
__device__ int g_cur[N_NODES];
__device__ int g_csr[N_EDGES];

// ---------------- CSR construction ----------------------------------------
__global__ void zero_deg_k() {
    int i = blockIdx.x * 256 + threadIdx.x;
    if (i < N_NODES) g_deg[i] = 0;
}

__global__ void hist_k(const int* __restrict__ ei) {
    int e = blockIdx.x * 256 + threadIdx.x;
    if (e < N_EDGES) atomicAdd(&g_deg[ei[N_EDGES + e]], 1);
}

// exclusive scan of 16384 ints, single block of 1024 threads, 16 elems each
__global__ void scan_k() {
    __shared__ int s[1024];
    int t = threadIdx.x;
    int base = t * 16;
    int local[16];
    int sum = 0;
#pragma unroll
    for (int i = 0; i < 16; i++) { local[i] = g_deg[base + i]; sum += local[i]; }
    s[t] = sum;
    __syncthreads();
    for (int d = 1; d < 1024; d <<= 1) {
        int v = 0;
        if (t >= d) v = s[t - d];
        __syncthreads();
        if (t >= d) s[t] += v;
        __syncthreads();
    }
    int prefix = (t == 0) ? 0 : s[t - 1];
    int run = prefix;
#pragma unroll
    for (int i = 0; i < 16; i++) { g_off[base + i] = run; run += local[i]; }
    if (t == 1023) g_off[N_NODES] = run;
}

__global__ void copy_cur_k() {
    int i = blockIdx.x * 256 + threadIdx.x;
    if (i < N_NODES) g_cur[i] = g_off[i];
}

__global__ void scatter_k(const int* __restrict__ ei) {
    int e = blockIdx.x * 256 + threadIdx.x;
    if (e < N_EDGES) {
        int d = ei[N_EDGES + e];
        int p = atomicAdd(&g_cur[d], 1);
        g_csr[p] = ei[e];
    }
}

// ---------------- SpMM: emb[i] = sum_{j in nbr(i)} ew[j] + eb --------------
__global__ void spmm_k(const float* __restrict__ ew,
                       const float* __restrict__ eb,
                       float* __restrict__ emb) {
    int node = blockIdx.x * 4 + (threadIdx.x >> 6);
    int c = threadIdx.x & 63;
    const float4* ew4 = (const float4*)ew;
    float4 acc = ((const float4*)eb)[c];
    int s = g_off[node];
    int e = g_off[node + 1];
    for (int k = s; k < e; k++) {
        int j = g_csr[k];
        float4 v = ew4[j * 64 + c];
        acc.x += v.x; acc.y += v.y; acc.z += v.z; acc.w += v.w;
    }
    ((float4*)emb)[node * 64 + c] = acc;
}

// ---------------- weight precompute ------------------------------------------
__global__ void addI_k(const float* __restrict__ w, float* __restrict__ outw) {
    int idx = blockIdx.x * 256 + threadIdx.x;   // 65536 elems
    int r = idx >> 8, c = idx & 255;
    outw[idx] = w[idx] + (r == c ? 1.f : 0.f);
}

__global__ void biasr_k(const float* __restrict__ nb,
                        const float* __restrict__ c1b,
                        const float* __restrict__ c2b) {
    int j = threadIdx.x;
    float s = c1b[j] + c2b[j];
    for (int k = 0; k < 256; k++) s += nb[k] * g_c2wp[k * 256 + j];
    g_biasr[j] = s;
}

// ---------------- fused, double-buffered GEMMs -------------------------------
// MODE 0: out = A@B1 + bias1
// MODE 1: out = relu(A@B1 + A2@B2 + bias1)     (K=512, two sources)
// MODE 2: out = relu(A@B1 + bias1), col sum/sumsq into g_sum/g_sq
// MODE 3: out = (A*g_scale[k]+g_shift[k])@B1 + bias1
//
// 128x128 tile, BK=16, 256 threads, 8x8 per thread, 2-stage smem pipeline.
template <int MODE>
__global__ void __launch_bounds__(256, 2)
gemm_k(const float* __restrict__ A, const float* __restrict__ A2,
       const float* __restrict__ B1, const float* __restrict__ B2,
       const float* __restrict__ bias1,
       float* __restrict__ outp, int ldout) {
    __shared__ float As[2][16][128];
    __shared__ float Bs[2][16][128];

    const int bm = blockIdx.y * 128;
    const int bn = blockIdx.x * 128;
    const int tid = threadIdx.x;
    const int tx = tid & 15;
    const int ty = tid >> 4;

    const int ar = tid >> 2;         // 0..63
    const int ac = (tid & 3) * 4;    // 0,4,8,12
    const int br = tid >> 5;         // 0..7
    const int bc = (tid & 31) * 4;   // 0..124

    const int T = (MODE == 1) ? 32 : 16;

    float4 ra0, ra1, rb0, rb1;

    auto LOAD = [&](int t) {
        const float* Ap = (MODE == 1 && t >= 16) ? A2 : A;
        const float* Bp = (MODE == 1 && t >= 16) ? B2 : B1;
        const int kt = (t & 15) * 16;
        ra0 = *(const float4*)(Ap + (bm + ar) * 256 + kt + ac);
        ra1 = *(const float4*)(Ap + (bm + ar + 64) * 256 + kt + ac);
        if (MODE == 3) {
            const int k0 = kt + ac;
            float s0 = g_scale[k0], s1 = g_scale[k0 + 1], s2 = g_scale[k0 + 2], s3 = g_scale[k0 + 3];
            float t0 = g_shift[k0], t1 = g_shift[k0 + 1], t2 = g_shift[k0 + 2], t3 = g_shift[k0 + 3];
            ra0.x = ra0.x * s0 + t0; ra0.y = ra0.y * s1 + t1;
            ra0.z = ra0.z * s2 + t2; ra0.w = ra0.w * s3 + t3;
            ra1.x = ra1.x * s0 + t0; ra1.y = ra1.y * s1 + t1;
            ra1.z = ra1.z * s2 + t2; ra1.w = ra1.w * s3 + t3;
        }
        rb0 = *(const float4*)(Bp + (kt + br) * 256 + bn + bc);
        rb1 = *(const float4*)(Bp + (kt + br + 8) * 256 + bn + bc);
    };

    auto STORE = [&](int b) {
        As[b][ac + 0][ar] = ra0.x;
        As[b][ac + 1][ar] = ra0.y;
        As[b][ac + 2][ar] = ra0.z;
        As[b][ac + 3][ar] = ra0.w;
        As[b][ac + 0][ar + 64] = ra1.x;
        As[b][ac + 1][ar + 64] = ra1.y;
        As[b][ac + 2][ar + 64] = ra1.z;
        As[b][ac + 3][ar + 64] = ra1.w;
        *(float4*)&Bs[b][br][bc]     = rb0;
        *(float4*)&Bs[b][br + 8][bc] = rb1;
    };

    float acc[8][8];
#pragma unroll
    for (int i = 0; i < 8; i++)
#pragma unroll
        for (int j = 0; j < 8; j++) acc[i][j] = 0.f;

    LOAD(0);
    STORE(0);
    __syncthreads();

    int buf = 0;
    for (int t = 0; t < T; t++) {
        if (t + 1 < T) LOAD(t + 1);
#pragma unroll
        for (int k = 0; k < 16; k++) {
            float af[8], bf[8];
            *(float4*)(af)     = *(const float4*)&As[buf][k][ty * 8];
            *(float4*)(af + 4) = *(const float4*)&As[buf][k][ty * 8 + 4];
            *(float4*)(bf)     = *(const float4*)&Bs[buf][k][tx * 8];
            *(float4*)(bf + 4) = *(const float4*)&Bs[buf][k][tx * 8 + 4];
#pragma unroll
            for (int i = 0; i < 8; i++)
#pragma unroll
                for (int j = 0; j < 8; j++)
                    acc[i][j] = fmaf(af[i], bf[j], acc[i][j]);
        }
        if (t + 1 < T) {
            STORE(buf ^ 1);
            __syncthreads();
            buf ^= 1;
        }
    }

    // epilogue
    float csum[8], csq[8];
#pragma unroll
    for (int j = 0; j < 8; j++) { csum[j] = 0.f; csq[j] = 0.f; }

#pragma unroll
    for (int i = 0; i < 8; i++) {
        int row = bm + ty * 8 + i;
        float o[8];
#pragma unroll
        for (int j = 0; j < 8; j++) {
            int col = bn + tx * 8 + j;
            float c = acc[i][j] + bias1[col];
            if (MODE == 1) c = fmaxf(c, 0.f);
            if (MODE == 2) {
                c = fmaxf(c, 0.f);
                csum[j] += c;
                csq[j] += c * c;
            }
            o[j] = c;
        }
        *(float4*)(outp + row * ldout + bn + tx * 8)     = *(float4*)(o);
        *(float4*)(outp + row * ldout + bn + tx * 8 + 4) = *(float4*)(o + 4);
    }

    if (MODE == 2) {
        __syncthreads();
#pragma unroll
        for (int j = 0; j < 8; j++) {
            As[0][ty][tx * 8 + j] = csum[j];
            Bs[0][ty][tx * 8 + j] = csq[j];
        }
        __syncthreads();
        if (tid < 128) {
            float s = 0.f, q = 0.f;
#pragma unroll
            for (int t = 0; t < 16; t++) { s += As[0][t][tid]; q += Bs[0][t][tid]; }
            atomicAdd(&g_sum[bn + tid], s);
            atomicAdd(&g_sq [bn + tid], q);
        }
    }
}

// ---------------- BN helpers -----------------------------------------------
__global__ void zero_stats_k() {
    int c = threadIdx.x;
    g_sum[c] = 0.f;
    g_sq[c] = 0.f;
}

__global__ void bn_prep_k(const float* __restrict__ gamma,
                          const float* __restrict__ beta) {
    int c = threadIdx.x;
    const float inv_n = 1.f / (float)N_NODES;
    float mu = g_sum[c] * inv_n;
    float var = g_sq[c] * inv_n - mu * mu;
    float rs = rsqrtf(var + BN_EPS);
    g_scale[c] = rs * gamma[c];
    g_shift[c] = beta[c] - mu * rs * gamma[c];
}

// ---------------- concat copy: out[:, 256:512] = x --------------------------
__global__ void copyx_k(const float* __restrict__ x, float* __restrict__ out) {
    int idx = blockIdx.x * 256 + threadIdx.x;
    int m = idx >> 6;
    int c = idx & 63;
    ((float4*)out)[m * 128 + 64 + c] = ((const float4*)x)[m * 64 + c];
}

// ---------------- host orchestration ----------------------------------------
static void run_layer(const float* xin, const float* const* P,
                      float* emb, float* r, float* q,
                      float* hout, int ldout,
                      float* w1p, float* c2wp, float* wx, float* biasr,
                      float* zerov) {
    // P: 0 ew, 1 eb, 2 nw, 3 nb, 4 c1w, 5 c1b, 6 c2w, 7 c2b,
    //    8 f1w, 9 f1b, 10 bng, 11 bnb, 12 f2w, 13 f2b
    dim3 grid(2, 128);

    spmm_k<<<N_NODES / 4, 256>>>(P[0], P[1], emb);
    addI_k<<<D_CH * D_CH / 256, 256>>>(P[4], w1p);
    addI_k<<<D_CH * D_CH / 256, 256>>>(P[6], c2wp);
    gemm_k<0><<<dim3(2, 2), 256>>>(P[2], nullptr, c2wp, nullptr, zerov, wx, 256);
    biasr_k<<<1, 256>>>(P[3], P[5], P[7]);
    // r = relu(emb @ w1p + x @ wx + biasr)
    gemm_k<1><<<grid, 256>>>(emb, xin, w1p, wx, biasr, r, 256);
    zero_stats_k<<<1, 256>>>();
    gemm_k<2><<<grid, 256>>>(r, nullptr, P[8], nullptr, P[9], q, 256);
    bn_prep_k<<<1, 256>>>(P[10], P[11]);
    gemm_k<3><<<grid, 256>>>(q, nullptr, P[12], nullptr, P[13], hout, ldout);
}

extern "C" void kernel_launch(void* const* d_in, const int* in_sizes, int n_in,
                              void* d_out, int out_size) {
    (void)in_sizes; (void)n_in; (void)out_size;

    const float* x  = (const float*)d_in[0];
    const int*   ei = (const int*)d_in[2];

    const float* P1[14];
    const float* P2[14];
    for (int i = 0; i < 14; i++) {
        P1[i] = (const float*)d_in[4 + i];
        P2[i] = (const float*)d_in[18 + i];
    }

    float *emb, *r, *q, *h, *w1p, *c2wp, *wx, *biasr, *zerov;
    cudaGetSymbolAddress((void**)&emb,   g_emb);
    cudaGetSymbolAddress((void**)&r,     g_r);
    cudaGetSymbolAddress((void**)&q,     g_q);
    cudaGetSymbolAddress((void**)&h,     g_h);
    cudaGetSymbolAddress((void**)&w1p,   g_w1p);
    cudaGetSymbolAddress((void**)&c2wp,  g_c2wp);
    cudaGetSymbolAddress((void**)&wx,    g_wx);
    cudaGetSymbolAddress((void**)&biasr, g_biasr);
    cudaGetSymbolAddress((void**)&zerov, g_zero);

    float* out = (float*)d_out;

    // CSR once (same graph for both layers)
    zero_deg_k<<<N_NODES / 256, 256>>>();
    hist_k<<<N_EDGES / 256, 256>>>(ei);
    scan_k<<<1, 1024>>>();
    copy_cur_k<<<N_NODES / 256, 256>>>();
    scatter_k<<<N_EDGES / 256, 256>>>(ei);

    // layer 1 -> g_h
    run_layer(x, P1, emb, r, q, h, 256, w1p, c2wp, wx, biasr, zerov);
    // layer 2 -> d_out[:, 0:256] (ld = 512)
    run_layer(h, P2, emb, r, q, out, 512, w1p, c2wp, wx, biasr, zerov);
    // d_out[:, 256:512] = x
    copyx_k<<<N_NODES * 64 / 256, 256>>>(x, out);
}

// round 4
// speedup vs baseline: 1.7750x; 1.6754x over previous
#include <cuda_runtime.h>
#include <cuda_bf16.h>

#define N_NODES 16384
#define N_EDGES 262144
#define D_CH    256
#define BN_EPS  1e-5f

// ================= device scratch (no runtime allocation) ==================
__device__ __nv_bfloat16 g_x_hi [N_NODES * D_CH];
__device__ __nv_bfloat16 g_x_lo [N_NODES * D_CH];
__device__ __nv_bfloat16 g_e_hi [N_NODES * D_CH];
__device__ __nv_bfloat16 g_e_lo [N_NODES * D_CH];
__device__ __nv_bfloat16 g_r_hi [N_NODES * D_CH];
__device__ __nv_bfloat16 g_r_lo [N_NODES * D_CH];
__device__ __nv_bfloat16 g_q_hi [N_NODES * D_CH];
__device__ __nv_bfloat16 g_q_lo [N_NODES * D_CH];
__device__ __nv_bfloat16 g_h_hi [N_NODES * D_CH];
__device__ __nv_bfloat16 g_h_lo [N_NODES * D_CH];

// stacked split weights, layout [N=256 rows][K'=768]: [hi | lo | hi]
__device__ __nv_bfloat16 g_Bw1[D_CH * 768];
__device__ __nv_bfloat16 g_Bwx[D_CH * 768];
__device__ __nv_bfloat16 g_Bf1[D_CH * 768];
__device__ __nv_bfloat16 g_Bf2[D_CH * 768];

__device__ float g_c2wp[D_CH * D_CH];   // I + c2w
__device__ float g_wx  [D_CH * D_CH];   // nw @ (I + c2w)
__device__ float g_biasr[D_CH];         // nb@(I+c2w) + c1b + c2b
__device__ float g_bias3[D_CH];         // f2b + shift @ f2w

__device__ float g_sum[D_CH];
__device__ float g_sq [D_CH];
__device__ float g_scale[D_CH];
__device__ float g_shift[D_CH];

__device__ int g_deg[N_NODES];
__device__ int g_off[N_NODES + 1];
__device__ int g_cur[N_NODES];
__device__ int g_csr[N_EDGES];

// ================= PTX helpers (sm_100 BASE ISA only) =======================
__device__ __forceinline__ unsigned smem_u32(const void* p) {
    unsigned a;
    asm("{ .reg .u64 t; cvta.to.shared.u64 t, %1; cvt.u32.u64 %0, t; }"
        : "=r"(a) : "l"(p));
    return a;
}

__device__ __forceinline__ void cp16(unsigned dst, const void* src) {
    asm volatile("cp.async.cg.shared.global [%0], [%1], 16;"
                 :: "r"(dst), "l"(src) : "memory");
}
__device__ __forceinline__ void cp_commit() {
    asm volatile("cp.async.commit_group;" ::: "memory");
}
template <int N>
__device__ __forceinline__ void cp_wait() {
    asm volatile("cp.async.wait_group %0;" :: "n"(N) : "memory");
}

__device__ __forceinline__ void ldsm_x4(unsigned* r, unsigned addr) {
    asm volatile("ldmatrix.sync.aligned.m8n8.x4.shared.b16 {%0,%1,%2,%3}, [%4];"
                 : "=r"(r[0]), "=r"(r[1]), "=r"(r[2]), "=r"(r[3]) : "r"(addr));
}

__device__ __forceinline__ void mma_bf16(float* c, const unsigned* a, const unsigned* b) {
    asm volatile(
        "mma.sync.aligned.m16n8k16.row.col.f32.bf16.bf16.f32 "
        "{%0,%1,%2,%3}, {%4,%5,%6,%7}, {%8,%9}, {%0,%1,%2,%3};"
        : "+f"(c[0]), "+f"(c[1]), "+f"(c[2]), "+f"(c[3])
        : "r"(a[0]), "r"(a[1]), "r"(a[2]), "r"(a[3]), "r"(b[0]), "r"(b[1]));
}

// split helpers
__device__ __forceinline__ void split1(float v, unsigned short& h, unsigned short& l) {
    __nv_bfloat16 hb = __float2bfloat16_rn(v);
    float r = v - __bfloat162float(hb);
    __nv_bfloat16 lb = __float2bfloat16_rn(r);
    h = __bfloat16_as_ushort(hb);
    l = __bfloat16_as_ushort(lb);
}
__device__ __forceinline__ void split4(float4 v, uint2& hi, uint2& lo) {
    unsigned short h0, h1, h2, h3, l0, l1, l2, l3;
    split1(v.x, h0, l0); split1(v.y, h1, l1);
    split1(v.z, h2, l2); split1(v.w, h3, l3);
    hi.x = (unsigned)h0 | ((unsigned)h1 << 16);
    hi.y = (unsigned)h2 | ((unsigned)h3 << 16);
    lo.x = (unsigned)l0 | ((unsigned)l1 << 16);
    lo.y = (unsigned)l2 | ((unsigned)l3 << 16);
}

// ================= CSR construction =========================================
__global__ void zero_deg_k() {
    int i = blockIdx.x * 256 + threadIdx.x;
    if (i < N_NODES) g_deg[i] = 0;
}
__global__ void hist_k(const int* __restrict__ ei) {
    int e = blockIdx.x * 256 + threadIdx.x;
    if (e < N_EDGES) atomicAdd(&g_deg[ei[N_EDGES + e]], 1);
}
__global__ void scan_k() {
    __shared__ int s[1024];
    int t = threadIdx.x;
    int base = t * 16;
    int local[16];
    int sum = 0;
#pragma unroll
    for (int i = 0; i < 16; i++) { local[i] = g_deg[base + i]; sum += local[i]; }
    s[t] = sum;
    __syncthreads();
    for (int d = 1; d < 1024; d <<= 1) {
        int v = 0;
        if (t >= d) v = s[t - d];
        __syncthreads();
        if (t >= d) s[t] += v;
        __syncthreads();
    }
    int prefix = (t == 0) ? 0 : s[t - 1];
    int run = prefix;
#pragma unroll
    for (int i = 0; i < 16; i++) { g_off[base + i] = run; run += local[i]; }
    if (t == 1023) g_off[N_NODES] = run;
}
__global__ void copy_cur_k() {
    int i = blockIdx.x * 256 + threadIdx.x;
    if (i < N_NODES) g_cur[i] = g_off[i];
}
__global__ void scatter_k(const int* __restrict__ ei) {
    int e = blockIdx.x * 256 + threadIdx.x;
    if (e < N_EDGES) {
        int d = ei[N_EDGES + e];
        int p = atomicAdd(&g_cur[d], 1);
        g_csr[p] = ei[e];
    }
}

// ================= SpMM -> split bf16 =======================================
__global__ void spmm_k(const float* __restrict__ ew, const float* __restrict__ eb,
                       __nv_bfloat16* __restrict__ ehi, __nv_bfloat16* __restrict__ elo) {
    int node = blockIdx.x * 4 + (threadIdx.x >> 6);
    int c = threadIdx.x & 63;
    const float4* ew4 = (const float4*)ew;
    float4 acc = ((const float4*)eb)[c];
    int s = g_off[node];
    int e = g_off[node + 1];
    for (int k = s; k < e; k++) {
        int j = g_csr[k];
        float4 v = ew4[j * 64 + c];
        acc.x += v.x; acc.y += v.y; acc.z += v.z; acc.w += v.w;
    }
    uint2 hi, lo;
    split4(acc, hi, lo);
    ((uint2*)ehi)[node * 64 + c] = hi;
    ((uint2*)elo)[node * 64 + c] = lo;
}

// ================= misc prep =================================================
__global__ void split_x_k(const float* __restrict__ x,
                          __nv_bfloat16* __restrict__ xhi,
                          __nv_bfloat16* __restrict__ xlo) {
    int i = blockIdx.x * 256 + threadIdx.x;
    float4 v = ((const float4*)x)[i];
    uint2 hi, lo;
    split4(v, hi, lo);
    ((uint2*)xhi)[i] = hi;
    ((uint2*)xlo)[i] = lo;
}

__global__ void addI_k(const float* __restrict__ w, float* __restrict__ outw) {
    int idx = blockIdx.x * 256 + threadIdx.x;
    int r = idx >> 8, c = idx & 255;
    outw[idx] = w[idx] + (r == c ? 1.f : 0.f);
}

__global__ void biasr_k(const float* __restrict__ nb, const float* __restrict__ c1b,
                        const float* __restrict__ c2b) {
    int j = threadIdx.x;
    float s = c1b[j] + c2b[j];
    for (int k = 0; k < 256; k++) s += nb[k] * g_c2wp[k * 256 + j];
    g_biasr[j] = s;
}

template <bool ADDI>
__global__ void split_w_k(const float* __restrict__ W, __nv_bfloat16* __restrict__ B) {
    int n = threadIdx.x, k = blockIdx.x;
    float w = W[(k << 8) + n];
    if (ADDI && k == n) w += 1.f;
    unsigned short h, l;
    split1(w, h, l);
    B[n * 768 + k]       = __ushort_as_bfloat16(h);
    B[n * 768 + 256 + k] = __ushort_as_bfloat16(l);
    B[n * 768 + 512 + k] = __ushort_as_bfloat16(h);
}

__global__ void fold_f2w_k(const float* __restrict__ W, __nv_bfloat16* __restrict__ B) {
    int n = threadIdx.x, k = blockIdx.x;
    float w = W[(k << 8) + n] * g_scale[k];
    unsigned short h, l;
    split1(w, h, l);
    B[n * 768 + k]       = __ushort_as_bfloat16(h);
    B[n * 768 + 256 + k] = __ushort_as_bfloat16(l);
    B[n * 768 + 512 + k] = __ushort_as_bfloat16(h);
}

__global__ void bias3_k(const float* __restrict__ f2w, const float* __restrict__ f2b) {
    int n = threadIdx.x;
    float s = f2b[n];
    for (int k = 0; k < 256; k++) s += g_shift[k] * f2w[k * 256 + n];
    g_bias3[n] = s;
}

// small fp32 GEMM: wx = nw @ c2wp, 256x256x256, 64x64 tiles
__global__ void wx_gemm_k(const float* __restrict__ A, const float* __restrict__ B,
                          float* __restrict__ C) {
    __shared__ float As[16][64];
    __shared__ float Bs[16][68];
    int bm = blockIdx.y * 64, bn = blockIdx.x * 64;
    int tx = threadIdx.x & 15, ty = threadIdx.x >> 4;
    float acc[4][4] = {};
    for (int kt = 0; kt < 256; kt += 16) {
        int r = threadIdx.x >> 2, c4 = (threadIdx.x & 3) * 4;
        float4 av = *(const float4*)(A + (bm + r) * 256 + kt + c4);
        As[c4 + 0][r] = av.x; As[c4 + 1][r] = av.y;
        As[c4 + 2][r] = av.z; As[c4 + 3][r] = av.w;
        int rb = threadIdx.x >> 4, cb = (threadIdx.x & 15) * 4;
        float4 bv = *(const float4*)(B + (kt + rb) * 256 + bn + cb);
        *(float4*)&Bs[rb][cb] = bv;
        __syncthreads();
#pragma unroll
        for (int k = 0; k < 16; k++) {
            float a[4], b[4];
#pragma unroll
            for (int i = 0; i < 4; i++) a[i] = As[k][ty * 4 + i];
#pragma unroll
            for (int j = 0; j < 4; j++) b[j] = Bs[k][tx * 4 + j];
#pragma unroll
            for (int i = 0; i < 4; i++)
#pragma unroll
                for (int j = 0; j < 4; j++) acc[i][j] = fmaf(a[i], b[j], acc[i][j]);
        }
        __syncthreads();
    }
#pragma unroll
    for (int i = 0; i < 4; i++)
#pragma unroll
        for (int j = 0; j < 4; j++)
            C[(bm + ty * 4 + i) * 256 + bn + tx * 4 + j] = acc[i][j];
}

// ================= BN helpers ================================================
__global__ void zero_stats_k() {
    int c = threadIdx.x;
    g_sum[c] = 0.f;
    g_sq[c] = 0.f;
}
__global__ void bn_prep_k(const float* __restrict__ gamma, const float* __restrict__ beta) {
    int c = threadIdx.x;
    const float inv_n = 1.f / (float)N_NODES;
    float mu = g_sum[c] * inv_n;
    float var = g_sq[c] * inv_n - mu * mu;
    float rs = rsqrtf(var + BN_EPS);
    g_scale[c] = rs * gamma[c];
    g_shift[c] = beta[c] - mu * rs * gamma[c];
}

__global__ void copyx_k(const float* __restrict__ x, float* __restrict__ out) {
    int idx = blockIdx.x * 256 + threadIdx.x;
    int m = idx >> 6;
    int c = idx & 63;
    ((float4*)out)[m * 128 + 64 + c] = ((const float4*)x)[m * 64 + c];
}

// ================= HMMA split-bf16 GEMM ======================================
// C[16384,256] = A(split)[16384,K'] @ B(stacked)[256,K'], K'=768 (MODE!=1) or
// 2x768 dual-source (MODE 1).
// MODE 1: relu epilogue; MODE 2: relu + BN stats; MODE 3: plain.
// F32S: fp32 store to outf (ldout); SPLITS: bf16 hi/lo store.
//
// CTA: 128(m) x 128(n), 8 warps of 32x64, 3-stage cp.async pipeline, k-chunk 64.
#define STAGES   3
#define BUF_SZ   32768                 // A 16KB + B 16KB
#define STATS_OFF (STAGES * BUF_SZ)    // 98304
#define SMEM_MMA (STATS_OFF + 1024)    // 99328

template <int MODE, bool F32S, bool SPLITS>
__global__ void __launch_bounds__(256, 2)
gemm_mma(const __nv_bfloat16* __restrict__ Ahi, const __nv_bfloat16* __restrict__ Alo,
         const __nv_bfloat16* __restrict__ A2hi, const __nv_bfloat16* __restrict__ A2lo,
         const __nv_bfloat16* __restrict__ Bb, const __nv_bfloat16* __restrict__ B2b,
         const float* __restrict__ bias,
         float* __restrict__ outf, int ldout,
         __nv_bfloat16* __restrict__ ohi, __nv_bfloat16* __restrict__ olo) {
    extern __shared__ char smem[];
    const unsigned sbase = smem_u32(smem);
    const int tid = threadIdx.x;
    const int lane = tid & 31;
    const int w = tid >> 5;
    const int wm = w & 3;          // m group: rows wm*32
    const int wn = w >> 2;         // n group: cols wn*64
    const int bm = blockIdx.y * 128;
    const int bn = blockIdx.x * 128;

    const int NC = (MODE == 1) ? 24 : 12;

    // ---- cp.async issue for chunk c into buffer c%STAGES ----
    auto issue = [&](int c) {
        const bool second = (MODE == 1) && (c >= 12);
        const int local = second ? c - 12 : c;
        const int p = local >> 2;
        const __nv_bfloat16* Ap = second ? (p == 2 ? A2lo : A2hi)
                                         : (p == 2 ? Alo  : Ahi);
        const __nv_bfloat16* Bp = second ? B2b : Bb;
        const int ka = (local & 3) << 6;
        const int kb = local << 6;
        const unsigned sa = sbase + (c % STAGES) * BUF_SZ;
        const unsigned sb = sa + 16384;
#pragma unroll
        for (int i = 0; i < 4; i++) {
            int u = tid + (i << 8);
            int row = u >> 3, seg = u & 7;
            cp16(sa + row * 128 + ((seg ^ (row & 7)) << 4),
                 Ap + ((bm + row) << 8) + ka + (seg << 3));
        }
#pragma unroll
        for (int i = 0; i < 4; i++) {
            int u = tid + (i << 8);
            int row = u >> 3, seg = u & 7;
            cp16(sb + row * 128 + ((seg ^ (row & 7)) << 4),
                 Bp + (bn + row) * 768 + kb + (seg << 3));
        }
        cp_commit();
    };

    // ---- ldmatrix lane addressing (fixed per thread) ----
    const int a_row = wm * 32 + (lane & 15);     // +mt*16 added later
    const int a_kh = lane >> 4;                  // k half (0/1)
    const int b_nrel = ((lane >> 4) << 3) + (lane & 7);
    const int b_n = wn * 64 + b_nrel;            // +np*16 added later
    const int b_kh = (lane >> 3) & 1;

    float acc[2][8][4];
#pragma unroll
    for (int mt = 0; mt < 2; mt++)
#pragma unroll
        for (int nt = 0; nt < 8; nt++)
#pragma unroll
            for (int q = 0; q < 4; q++) acc[mt][nt][q] = 0.f;

    // prologue: fill the pipe
    issue(0); issue(1); issue(2);

    for (int c = 0; c < NC; c++) {
        cp_wait<STAGES - 1>();
        __syncthreads();
        const unsigned sa = sbase + (c % STAGES) * BUF_SZ;
        const unsigned sb = sa + 16384;
#pragma unroll
        for (int ks = 0; ks < 4; ks++) {
            const int seg0 = ks * 2;     // k0 = ks*16 -> seg = k0/8
            unsigned af[2][4];
#pragma unroll
            for (int mt = 0; mt < 2; mt++) {
                int r = a_row + mt * 16;
                ldsm_x4(af[mt], sa + r * 128 + (((seg0 + a_kh) ^ (r & 7)) << 4));
            }
            unsigned bf[8][2];
#pragma unroll
            for (int np = 0; np < 4; np++) {
                int n = b_n + np * 16;
                unsigned t4[4];
                ldsm_x4(t4, sb + n * 128 + (((seg0 + b_kh) ^ (n & 7)) << 4));
                bf[np * 2][0] = t4[0]; bf[np * 2][1] = t4[1];
                bf[np * 2 + 1][0] = t4[2]; bf[np * 2 + 1][1] = t4[3];
            }
#pragma unroll
            for (int mt = 0; mt < 2; mt++)
#pragma unroll
                for (int nt = 0; nt < 8; nt++)
                    mma_bf16(acc[mt][nt], af[mt], bf[nt]);
        }
        __syncthreads();
        if (c + STAGES < NC) issue(c + STAGES);
    }
    __syncthreads();   // pipeline buffers now reusable as staging

    // ---- epilogue: regs -> staged fp32 tile (swizzled, 128 x 512B) ----
    const int er = lane >> 2;            // 0..7
    const int ec = (lane & 3) << 1;      // 0,2,4,6
#pragma unroll
    for (int mt = 0; mt < 2; mt++) {
#pragma unroll
        for (int nt = 0; nt < 8; nt++) {
            int r0 = wm * 32 + mt * 16 + er;
            int cc = wn * 64 + nt * 8 + ec;
            float b0 = bias[bn + cc], b1 = bias[bn + cc + 1];
            float v0 = acc[mt][nt][0] + b0, v1 = acc[mt][nt][1] + b1;
            float v2 = acc[mt][nt][2] + b0, v3 = acc[mt][nt][3] + b1;
            if (MODE == 1 || MODE == 2) {
                v0 = fmaxf(v0, 0.f); v1 = fmaxf(v1, 0.f);
                v2 = fmaxf(v2, 0.f); v3 = fmaxf(v3, 0.f);
            }
            int r1 = r0 + 8;
            float2 p0 = make_float2(v0, v1), p1 = make_float2(v2, v3);
            *(float2*)(smem + r0 * 512 + ((((cc >> 2) ^ ((r0 & 7) << 2))) << 4) + ((cc & 3) << 2)) = p0;
            *(float2*)(smem + r1 * 512 + ((((cc >> 2) ^ ((r1 & 7) << 2))) << 4) + ((cc & 3) << 2)) = p1;
        }
    }
    __syncthreads();

    // ---- staged -> global (coalesced float4) ----
#pragma unroll 4
    for (int i = 0; i < 16; i++) {
        int u = tid + (i << 8);
        int r = u >> 5, seg = u & 31;
        float4 v = *(const float4*)(smem + r * 512 + ((seg ^ ((r & 7) << 2)) << 4));
        int grow = bm + r;
        int gcol = bn + (seg << 2);
        if (F32S) *(float4*)(outf + grow * ldout + gcol) = v;
        if (SPLITS) {
            uint2 hi, lo;
            split4(v, hi, lo);
            ((uint2*)ohi)[(grow << 6) + (gcol >> 2)] = hi;
            ((uint2*)olo)[(grow << 6) + (gcol >> 2)] = lo;
        }
    }

    // ---- BN stats (MODE 2) from staged tile ----
    if (MODE == 2) {
        int c = tid & 127, r0 = (tid >> 7) << 6;
        float s = 0.f, q = 0.f;
#pragma unroll 4
        for (int rr = 0; rr < 64; rr++) {
            int r = r0 + rr;
            float v = *(const float*)(smem + r * 512 +
                                      ((((c >> 2) ^ ((r & 7) << 2))) << 4) + ((c & 3) << 2));
            s += v;
            q += v * v;
        }
        float* st = (float*)(smem + STATS_OFF);
        if (tid >= 128) { st[c] = s; st[128 + c] = q; }
        __syncthreads();
        if (tid < 128) {
            atomicAdd(&g_sum[bn + c], s + st[c]);
            atomicAdd(&g_sq [bn + c], q + st[128 + c]);
        }
    }
}

// ================= host orchestration ========================================
static void run_layer(const __nv_bfloat16* xin_hi, const __nv_bfloat16* xin_lo,
                      const float* const* P,
                      float* out_f32, int ldout, bool store_f32,
                      __nv_bfloat16* e_hi, __nv_bfloat16* e_lo,
                      __nv_bfloat16* r_hi, __nv_bfloat16* r_lo,
                      __nv_bfloat16* q_hi, __nv_bfloat16* q_lo,
                      __nv_bfloat16* h_hi, __nv_bfloat16* h_lo,
                      float* c2wp, float* wx,
                      __nv_bfloat16* Bw1, __nv_bfloat16* Bwx,
                      __nv_bfloat16* Bf1, __nv_bfloat16* Bf2) {
    // P: 0 ew, 1 eb, 2 nw, 3 nb, 4 c1w, 5 c1b, 6 c2w, 7 c2b,
    //    8 f1w, 9 f1b, 10 bng, 11 bnb, 12 f2w, 13 f2b
    dim3 grid(2, 128);

    spmm_k<<<N_NODES / 4, 256>>>(P[0], P[1], e_hi, e_lo);
    addI_k<<<D_CH * D_CH / 256, 256>>>(P[6], c2wp);
    wx_gemm_k<<<dim3(4, 4), 256>>>(P[2], c2wp, wx);
    biasr_k<<<1, 256>>>(P[3], P[5], P[7]);
    split_w_k<true><<<256, 256>>>(P[4], Bw1);
    split_w_k<false><<<256, 256>>>(wx, Bwx);
    split_w_k<false><<<256, 256>>>(P[8], Bf1);

    float* br;  cudaGetSymbolAddress((void**)&br, g_biasr);
    float* b3;  cudaGetSymbolAddress((void**)&b3, g_bias3);

    // r = relu(emb @ (I+c1w) + x @ wx + biasr)
    gemm_mma<1, false, true><<<grid, 256, SMEM_MMA>>>(
        e_hi, e_lo, xin_hi, xin_lo, Bw1, Bwx, br, nullptr, 0, r_hi, r_lo);
    zero_stats_k<<<1, 256>>>();
    // q = relu(r @ f1w + f1b), BN stats
    gemm_mma<2, false, true><<<grid, 256, SMEM_MMA>>>(
        r_hi, r_lo, r_hi, r_lo, Bf1, Bf1, P[9], nullptr, 0, q_hi, q_lo);
    bn_prep_k<<<1, 256>>>(P[10], P[11]);
    fold_f2w_k<<<256, 256>>>(P[12], Bf2);
    bias3_k<<<1, 256>>>(P[12], P[13]);
    // h = (q*scale + shift) @ f2w + f2b   (BN folded into B + bias)
    if (store_f32) {
        gemm_mma<3, true, false><<<grid, 256, SMEM_MMA>>>(
            q_hi, q_lo, q_hi, q_lo, Bf2, Bf2, b3, out_f32, ldout, h_hi, h_lo);
    } else {
        gemm_mma<3, false, true><<<grid, 256, SMEM_MMA>>>(
            q_hi, q_lo, q_hi, q_lo, Bf2, Bf2, b3, nullptr, 0, h_hi, h_lo);
    }
}

extern "C" void kernel_launch(void* const* d_in, const int* in_sizes, int n_in,
                              void* d_out, int out_size) {
    (void)in_sizes; (void)n_in; (void)out_size;

    const float* x  = (const float*)d_in[0];
    const int*   ei = (const int*)d_in[2];

    const float* P1[14];
    const float* P2[14];
    for (int i = 0; i < 14; i++) {
        P1[i] = (const float*)d_in[4 + i];
        P2[i] = (const float*)d_in[18 + i];
    }

    cudaFuncSetAttribute(gemm_mma<1, false, true>,
                         cudaFuncAttributeMaxDynamicSharedMemorySize, SMEM_MMA);
    cudaFuncSetAttribute(gemm_mma<2, false, true>,
                         cudaFuncAttributeMaxDynamicSharedMemorySize, SMEM_MMA);
    cudaFuncSetAttribute(gemm_mma<3, false, true>,
                         cudaFuncAttributeMaxDynamicSharedMemorySize, SMEM_MMA);
    cudaFuncSetAttribute(gemm_mma<3, true, false>,
                         cudaFuncAttributeMaxDynamicSharedMemorySize, SMEM_MMA);

    __nv_bfloat16 *x_hi, *x_lo, *e_hi, *e_lo, *r_hi, *r_lo, *q_hi, *q_lo, *h_hi, *h_lo;
    __nv_bfloat16 *Bw1, *Bwx, *Bf1, *Bf2;
    float *c2wp, *wx;
    cudaGetSymbolAddress((void**)&x_hi, g_x_hi);
    cudaGetSymbolAddress((void**)&x_lo, g_x_lo);
    cudaGetSymbolAddress((void**)&e_hi, g_e_hi);
    cudaGetSymbolAddress((void**)&e_lo, g_e_lo);
    cudaGetSymbolAddress((void**)&r_hi, g_r_hi);
    cudaGetSymbolAddress((void**)&r_lo, g_r_lo);
    cudaGetSymbolAddress((void**)&q_hi, g_q_hi);
    cudaGetSymbolAddress((void**)&q_lo, g_q_lo);
    cudaGetSymbolAddress((void**)&h_hi, g_h_hi);
    cudaGetSymbolAddress((void**)&h_lo, g_h_lo);
    cudaGetSymbolAddress((void**)&Bw1, g_Bw1);
    cudaGetSymbolAddress((void**)&Bwx, g_Bwx);
    cudaGetSymbolAddress((void**)&Bf1, g_Bf1);
    cudaGetSymbolAddress((void**)&Bf2, g_Bf2);
    cudaGetSymbolAddress((void**)&c2wp, g_c2wp);
    cudaGetSymbolAddress((void**)&wx, g_wx);

    float* out = (float*)d_out;

    // CSR once (same graph for both layers)
    zero_deg_k<<<N_NODES / 256, 256>>>();
    hist_k<<<N_EDGES / 256, 256>>>(ei);
    scan_k<<<1, 1024>>>();
    copy_cur_k<<<N_NODES / 256, 256>>>();
    scatter_k<<<N_EDGES / 256, 256>>>(ei);

    // split x once
    split_x_k<<<N_NODES * 64 / 256, 256>>>(x, x_hi, x_lo);

    // layer 1 -> h (split only)
    run_layer(x_hi, x_lo, P1, nullptr, 0, false,
              e_hi, e_lo, r_hi, r_lo, q_hi, q_lo, h_hi, h_lo,
              c2wp, wx, Bw1, Bwx, Bf1, Bf2);
    // layer 2 -> d_out[:, 0:256] (ld = 512), fp32
    run_layer(h_hi, h_lo, P2, out, 512, true,
              e_hi, e_lo, r_hi, r_lo, q_hi, q_lo, h_hi, h_lo,
              c2wp, wx, Bw1, Bwx, Bf1, Bf2);
    // d_out[:, 256:512] = x
    copyx_k<<<N_NODES * 64 / 256, 256>>>(x, out);
}